// round 10
// baseline (speedup 1.0000x reference)
#include <cuda_runtime.h>
#include <cuda_fp16.h>

#define Bdim 2
#define Sdim 512
#define Fdim 16384
#define Ddim 768
#define Mdim 262144
#define BS   (Bdim * Sdim)       // 1024
#define D4   (Ddim / 4)          // 192

// -------- device scratch (static, no allocation) --------
__device__ uint2  g_Uth[(size_t)Fdim * 192];    // up_decoder^T [F, 768] fp16, 24 MB
__device__ uint2  g_Xh[(size_t)Fdim * 256];     // up_facts^T   [F,1024] fp16, 32 MB
__device__ float  g_vals[Mdim];
__device__ int    g_ii[Mdim];
__device__ int    g_jj[Mdim];
__device__ int    g_rowptr[Fdim + 1];

// -------- index convert, dtype detected inline (broadcast load) --------
__global__ void k_convert(const void* __restrict__ ip, const void* __restrict__ jp) {
    long long probe = ((const long long*)ip)[65536];
    bool is64 = (probe >= 0 && probe < (long long)Fdim);
    int m = blockIdx.x * blockDim.x + threadIdx.x;
    if (m >= Mdim) return;
    if (is64) {
        g_ii[m] = (int)((const long long*)ip)[m];
        g_jj[m] = (int)((const long long*)jp)[m];
    } else {
        g_ii[m] = ((const int*)ip)[m];
        g_jj[m] = ((const int*)jp)[m];
    }
}

// -------- CSR row pointers via boundary scatter (i sorted) --------
__global__ void k_rowptr() {
    int m = blockIdx.x * blockDim.x + threadIdx.x;
    if (m >= Mdim) return;
    int cur  = g_ii[m];
    int prev = (m == 0) ? -1 : g_ii[m - 1];
    for (int r = prev + 1; r <= cur; ++r) g_rowptr[r] = m;
    if (m == Mdim - 1)
        for (int r = cur + 1; r <= Fdim; ++r) g_rowptr[r] = Mdim;
}

// -------- fused transpose + fp32->fp16, 64x64 tiles, half2-packed smem ----
__device__ __forceinline__ void trans_h2_tile(const float* __restrict__ src,
                                              uint* __restrict__ dst,
                                              int nrows, int bx, int by) {
    __shared__ uint tile[64][33];
    int t   = threadIdx.x;
    int c   = t & 63;
    int rp0 = t >> 6;
#pragma unroll
    for (int it = 0; it < 8; it++) {
        int rp = rp0 + it * 4;
        int r  = by + 2 * rp;
        float a = src[(size_t)r * Fdim + bx + c];
        float b = src[(size_t)(r + 1) * Fdim + bx + c];
        __half2 h = __floats2half2_rn(a, b);
        tile[c][rp] = *(uint*)&h;
    }
    __syncthreads();
    int lane = t & 31;
    int f0   = t >> 5;
    int rowu = nrows >> 1;
#pragma unroll
    for (int it = 0; it < 8; it++) {
        int f = f0 + it * 8;
        dst[(size_t)(bx + f) * rowu + (by >> 1) + lane] = tile[f][lane];
    }
}

__global__ void __launch_bounds__(256) k_trans(const float* __restrict__ U,
                                               const float* __restrict__ X) {
    int bx = blockIdx.x * 64;
    int y  = blockIdx.y;
    if (y < 12) trans_h2_tile(U, (uint*)g_Uth, Ddim, bx, y * 64);
    else        trans_h2_tile(X, (uint*)g_Xh,  BS,  bx, (y - 12) * 64);
}

// -------- values: one block (256 thr) per row i. Dn[i] + j-list staged in
// smem; each warp computes TWO connection dots concurrently (12 LDGs deep). --
#define VJC 128
__global__ void __launch_bounds__(256) k_values(const float* __restrict__ Dn) {
    __shared__ float4 sD[192];          // 3 KB
    __shared__ int    sJ[VJC];          // 512 B
    int i    = blockIdx.x;
    int t    = threadIdx.x;
    int wid  = t >> 5, lane = t & 31;

    const float4* __restrict__ Dr = (const float4*)Dn + (size_t)i * D4;
    if (t < 192) sD[t] = Dr[t];

    int mb = g_rowptr[i], me = g_rowptr[i + 1];
    int nnz = me - mb;
    for (int p = t; p < nnz && p < VJC; p += 256) sJ[p] = g_jj[mb + p];
    __syncthreads();

    for (int p = 2 * wid; p < nnz; p += 16) {
        int  p1   = p + 1;
        bool has1 = (p1 < nnz);
        int j0 = (p  < VJC) ? sJ[p]  : g_jj[mb + p];
        int j1 = has1 ? ((p1 < VJC) ? sJ[p1] : g_jj[mb + p1]) : j0;
        const uint2* __restrict__ U0 = g_Uth + (size_t)j0 * 192;
        const uint2* __restrict__ U1 = g_Uth + (size_t)j1 * 192;
        float s0 = 0.f, s1 = 0.f;
#pragma unroll
        for (int k = 0; k < 6; k++) {
            int idx = k * 32 + lane;
            uint2  u0 = U0[idx];
            uint2  u1 = U1[idx];
            float4 d  = sD[idx];
            float2 a0 = __half22float2(*(const __half2*)&u0.x);
            float2 b0 = __half22float2(*(const __half2*)&u0.y);
            float2 a1 = __half22float2(*(const __half2*)&u1.x);
            float2 b1 = __half22float2(*(const __half2*)&u1.y);
            s0 += d.x * a0.x + d.y * a0.y + d.z * b0.x + d.w * b0.y;
            s1 += d.x * a1.x + d.y * a1.y + d.z * b1.x + d.w * b1.y;
        }
#pragma unroll
        for (int o = 16; o > 0; o >>= 1) {
            s0 += __shfl_xor_sync(0xffffffffu, s0, o);
            s1 += __shfl_xor_sync(0xffffffffu, s1, o);
        }
        if (lane == 0) {
            g_vals[mb + p] = s0;
            if (has1) g_vals[mb + p1] = s1;
        }
    }
}

// -------- accumulate helper --------
__device__ __forceinline__ void acc_px(float4& a, float v, uint2 px) {
    float2 lo = __half22float2(*(const __half2*)&px.x);
    float2 hi = __half22float2(*(const __half2*)&px.y);
    a.x += v * lo.x; a.y += v * lo.y;
    a.z += v * hi.x; a.w += v * hi.y;
}

// -------- fused SpMM + output transpose; block indices+vals staged in smem --
#define SR   8
#define SCAP 256
__device__ __forceinline__ void jv_get(int o, int m, const int* sJJ,
                                       const float* sVV, int& j, float& v) {
    if (o < SCAP) { j = sJJ[o]; v = sVV[o]; }
    else          { j = g_jj[m]; v = g_vals[m]; }
}

__global__ void __launch_bounds__(256) k_spmm(float* __restrict__ out) {
    __shared__ float stage[SR][1028];   // 32.9 KB
    __shared__ int   sJJ[SCAP];         // 1 KB
    __shared__ float sVV[SCAP];         // 1 KB
    int t  = threadIdx.x;
    int r0 = blockIdx.x * SR;

    int ms  = g_rowptr[r0];
    int cnt = g_rowptr[r0 + SR] - ms;
    for (int p = t; p < cnt && p < SCAP; p += 256) {
        sJJ[p] = g_jj[ms + p];
        sVV[p] = g_vals[ms + p];
    }
    __syncthreads();

#pragma unroll 1
    for (int rr = 0; rr < SR; rr++) {
        int r  = r0 + rr;
        int m  = g_rowptr[r], me = g_rowptr[r + 1];
        float4 a = make_float4(0.f, 0.f, 0.f, 0.f);

        for (; m + 4 <= me; m += 4) {
            int o = m - ms;
            int j0, j1, j2, j3; float v0, v1, v2, v3;
            jv_get(o,     m,     sJJ, sVV, j0, v0);
            jv_get(o + 1, m + 1, sJJ, sVV, j1, v1);
            jv_get(o + 2, m + 2, sJJ, sVV, j2, v2);
            jv_get(o + 3, m + 3, sJJ, sVV, j3, v3);
            uint2 x0 = g_Xh[(size_t)j0 * 256 + t];
            uint2 x1 = g_Xh[(size_t)j1 * 256 + t];
            uint2 x2 = g_Xh[(size_t)j2 * 256 + t];
            uint2 x3 = g_Xh[(size_t)j3 * 256 + t];
            acc_px(a, v0, x0); acc_px(a, v1, x1);
            acc_px(a, v2, x2); acc_px(a, v3, x3);
        }
        for (; m < me; ++m) {
            int o = m - ms;
            int j; float v;
            jv_get(o, m, sJJ, sVV, j, v);
            uint2 x = g_Xh[(size_t)j * 256 + t];
            acc_px(a, v, x);
        }
        *(float4*)&stage[rr][4 * t] = a;
    }
    __syncthreads();

#pragma unroll
    for (int it = 0; it < 8; it++) {
        int g  = it * 256 + t;
        int c  = g & 1;
        int bs = g >> 1;
        float4 o;
        o.x = stage[4 * c + 0][bs];
        o.y = stage[4 * c + 1][bs];
        o.z = stage[4 * c + 2][bs];
        o.w = stage[4 * c + 3][bs];
        *(float4*)&out[(size_t)bs * Fdim + r0 + 4 * c] = o;
    }
}

extern "C" void kernel_launch(void* const* d_in, const int* in_sizes, int n_in,
                              void* d_out, int out_size) {
    const float* up_facts = (const float*)d_in[0];   // [B, S, F] fp32
    const float* down_enc = (const float*)d_in[1];   // [F, D]    fp32
    const float* up_dec   = (const float*)d_in[2];   // [D, F]    fp32
    const void*  iI       = d_in[3];                 // [M] int64 (or int32)
    const void*  jI       = d_in[4];                 // [M] int64 (or int32)
    float*       out      = (float*)d_out;           // [B, S, F] fp32

    k_convert<<<Mdim / 256, 256>>>(iI, jI);

    k_trans<<<dim3(Fdim / 64, 12 + BS / 64), 256>>>(up_dec, up_facts);

    k_rowptr<<<Mdim / 256, 256>>>();

    k_values<<<Fdim, 256>>>(down_enc);

    k_spmm<<<Fdim / SR, 256>>>(out);
}

// round 11
// speedup vs baseline: 1.1282x; 1.1282x over previous
#include <cuda_runtime.h>
#include <cuda_fp16.h>

#define Bdim 2
#define Sdim 512
#define Fdim 16384
#define Ddim 768
#define Mdim 262144
#define BS   (Bdim * Sdim)       // 1024
#define D4   (Ddim / 4)          // 192

// -------- device scratch (static, no allocation) --------
__device__ uint2  g_Uth[(size_t)Fdim * 192];    // up_decoder^T [F, 768] fp16, 24 MB
__device__ uint2  g_Xh[(size_t)Fdim * 256];     // up_facts^T   [F,1024] fp16, 32 MB
__device__ float  g_vals[Mdim];
__device__ int    g_ii[Mdim];
__device__ int    g_jj[Mdim];
__device__ int    g_rowptr[Fdim + 1];

// -------- index convert, dtype detected inline (broadcast load) --------
__global__ void k_convert(const void* __restrict__ ip, const void* __restrict__ jp) {
    long long probe = ((const long long*)ip)[65536];
    bool is64 = (probe >= 0 && probe < (long long)Fdim);
    int m = blockIdx.x * blockDim.x + threadIdx.x;
    if (m >= Mdim) return;
    if (is64) {
        g_ii[m] = (int)((const long long*)ip)[m];
        g_jj[m] = (int)((const long long*)jp)[m];
    } else {
        g_ii[m] = ((const int*)ip)[m];
        g_jj[m] = ((const int*)jp)[m];
    }
}

// -------- CSR row pointers via boundary scatter (i sorted) --------
__global__ void k_rowptr() {
    int m = blockIdx.x * blockDim.x + threadIdx.x;
    if (m >= Mdim) return;
    int cur  = g_ii[m];
    int prev = (m == 0) ? -1 : g_ii[m - 1];
    for (int r = prev + 1; r <= cur; ++r) g_rowptr[r] = m;
    if (m == Mdim - 1)
        for (int r = cur + 1; r <= Fdim; ++r) g_rowptr[r] = Mdim;
}

// -------- fused transpose + fp32->fp16, 64x64 tiles, half2-packed smem ----
__device__ __forceinline__ void trans_h2_tile(const float* __restrict__ src,
                                              uint* __restrict__ dst,
                                              int nrows, int bx, int by) {
    __shared__ uint tile[64][33];
    int t   = threadIdx.x;
    int c   = t & 63;
    int rp0 = t >> 6;
#pragma unroll
    for (int it = 0; it < 8; it++) {
        int rp = rp0 + it * 4;
        int r  = by + 2 * rp;
        float a = src[(size_t)r * Fdim + bx + c];
        float b = src[(size_t)(r + 1) * Fdim + bx + c];
        __half2 h = __floats2half2_rn(a, b);
        tile[c][rp] = *(uint*)&h;
    }
    __syncthreads();
    int lane = t & 31;
    int f0   = t >> 5;
    int rowu = nrows >> 1;
#pragma unroll
    for (int it = 0; it < 8; it++) {
        int f = f0 + it * 8;
        dst[(size_t)(bx + f) * rowu + (by >> 1) + lane] = tile[f][lane];
    }
}

__global__ void __launch_bounds__(256) k_trans(const float* __restrict__ U,
                                               const float* __restrict__ X) {
    int bx = blockIdx.x * 64;
    int y  = blockIdx.y;
    if (y < 12) trans_h2_tile(U, (uint*)g_Uth, Ddim, bx, y * 64);
    else        trans_h2_tile(X, (uint*)g_Xh,  BS,  bx, (y - 12) * 64);
}

// -------- values: one block (128 thr = 4 warps) per row i. Dn[i] + j-list in
// smem; each warp runs TWO connection dots concurrently (12 LDG.64 in flight).
// Pair stride 8: nnz=16 -> every warp gets exactly 2 iterations, none idle. --
#define VJC 64
__global__ void __launch_bounds__(128) k_values(const float* __restrict__ Dn) {
    __shared__ float4 sD[192];          // 3 KB
    __shared__ int    sJ[VJC];          // 256 B
    int i    = blockIdx.x;
    int t    = threadIdx.x;
    int wid  = t >> 5, lane = t & 31;

    const float4* __restrict__ Dr = (const float4*)Dn + (size_t)i * D4;
    if (t < 192) sD[t] = Dr[t];
    if (t + 128 < 192) sD[t + 128] = Dr[t + 128];

    int mb = g_rowptr[i], me = g_rowptr[i + 1];
    int nnz = me - mb;
    for (int p = t; p < nnz && p < VJC; p += 128) sJ[p] = g_jj[mb + p];
    __syncthreads();

    for (int p = 2 * wid; p < nnz; p += 8) {
        int  p1   = p + 1;
        bool has1 = (p1 < nnz);
        int j0 = (p  < VJC) ? sJ[p]  : g_jj[mb + p];
        int j1 = has1 ? ((p1 < VJC) ? sJ[p1] : g_jj[mb + p1]) : j0;
        const uint2* __restrict__ U0 = g_Uth + (size_t)j0 * 192;
        const uint2* __restrict__ U1 = g_Uth + (size_t)j1 * 192;
        float s0 = 0.f, s1 = 0.f;
#pragma unroll
        for (int k = 0; k < 6; k++) {
            int idx = k * 32 + lane;
            uint2  u0 = U0[idx];
            uint2  u1 = U1[idx];
            float4 d  = sD[idx];
            float2 a0 = __half22float2(*(const __half2*)&u0.x);
            float2 b0 = __half22float2(*(const __half2*)&u0.y);
            float2 a1 = __half22float2(*(const __half2*)&u1.x);
            float2 b1 = __half22float2(*(const __half2*)&u1.y);
            s0 += d.x * a0.x + d.y * a0.y + d.z * b0.x + d.w * b0.y;
            s1 += d.x * a1.x + d.y * a1.y + d.z * b1.x + d.w * b1.y;
        }
#pragma unroll
        for (int o = 16; o > 0; o >>= 1) {
            s0 += __shfl_xor_sync(0xffffffffu, s0, o);
            s1 += __shfl_xor_sync(0xffffffffu, s1, o);
        }
        if (lane == 0) {
            g_vals[mb + p] = s0;
            if (has1) g_vals[mb + p1] = s1;
        }
    }
}

// -------- accumulate helper --------
__device__ __forceinline__ void acc_px(float4& a, float v, uint2 px) {
    float2 lo = __half22float2(*(const __half2*)&px.x);
    float2 hi = __half22float2(*(const __half2*)&px.y);
    a.x += v * lo.x; a.y += v * lo.y;
    a.z += v * hi.x; a.w += v * hi.y;
}

// -------- fused SpMM + output transpose, MLP-4 gather batches (R8 version) --
#define SR 8
__global__ void __launch_bounds__(256) k_spmm(float* __restrict__ out) {
    __shared__ float stage[SR][1028];
    int t  = threadIdx.x;
    int r0 = blockIdx.x * SR;

#pragma unroll 1
    for (int rr = 0; rr < SR; rr++) {
        int r  = r0 + rr;
        int m  = g_rowptr[r], me = g_rowptr[r + 1];
        float4 a = make_float4(0.f, 0.f, 0.f, 0.f);

        for (; m + 4 <= me; m += 4) {
            int   j0 = g_jj[m],     j1 = g_jj[m + 1];
            int   j2 = g_jj[m + 2], j3 = g_jj[m + 3];
            float v0 = g_vals[m],     v1 = g_vals[m + 1];
            float v2 = g_vals[m + 2], v3 = g_vals[m + 3];
            uint2 x0 = g_Xh[(size_t)j0 * 256 + t];
            uint2 x1 = g_Xh[(size_t)j1 * 256 + t];
            uint2 x2 = g_Xh[(size_t)j2 * 256 + t];
            uint2 x3 = g_Xh[(size_t)j3 * 256 + t];
            acc_px(a, v0, x0); acc_px(a, v1, x1);
            acc_px(a, v2, x2); acc_px(a, v3, x3);
        }
        for (; m < me; ++m) {
            int   j = g_jj[m];
            float v = g_vals[m];
            uint2 x = g_Xh[(size_t)j * 256 + t];
            acc_px(a, v, x);
        }
        *(float4*)&stage[rr][4 * t] = a;
    }
    __syncthreads();

#pragma unroll
    for (int it = 0; it < 8; it++) {
        int g  = it * 256 + t;
        int c  = g & 1;
        int bs = g >> 1;
        float4 o;
        o.x = stage[4 * c + 0][bs];
        o.y = stage[4 * c + 1][bs];
        o.z = stage[4 * c + 2][bs];
        o.w = stage[4 * c + 3][bs];
        *(float4*)&out[(size_t)bs * Fdim + r0 + 4 * c] = o;
    }
}

extern "C" void kernel_launch(void* const* d_in, const int* in_sizes, int n_in,
                              void* d_out, int out_size) {
    const float* up_facts = (const float*)d_in[0];   // [B, S, F] fp32
    const float* down_enc = (const float*)d_in[1];   // [F, D]    fp32
    const float* up_dec   = (const float*)d_in[2];   // [D, F]    fp32
    const void*  iI       = d_in[3];                 // [M] int64 (or int32)
    const void*  jI       = d_in[4];                 // [M] int64 (or int32)
    float*       out      = (float*)d_out;           // [B, S, F] fp32

    k_convert<<<Mdim / 256, 256>>>(iI, jI);

    k_trans<<<dim3(Fdim / 64, 12 + BS / 64), 256>>>(up_dec, up_facts);

    k_rowptr<<<Mdim / 256, 256>>>();

    k_values<<<Fdim, 128>>>(down_enc);

    k_spmm<<<Fdim / SR, 256>>>(out);
}